// round 10
// baseline (speedup 1.0000x reference)
#include <cuda_runtime.h>

#define NB 16
#define NP 65536
#define NT 64
#define GB 16                 /* bins per dimension */
#define NBIN (GB*GB)          /* 256 bins per batch */
#define BBLK 16               /* binning blocks per batch */
#define APB (NP/BBLK)         /* 4096 anchors per binning block */

// ---- k_match config (R6 proven shape) ----
#define THR_M 256
#define APT 4
#define CHUNK (THR_M*APT)     /* 1024 anchors per block; each warp owns 128 binned slots */

// ---- k_loss config (R6/R9 proven grid shape) ----
#define THR_L 256
#define LBLKX (NP/(THR_L*4))  /* 64 blocks per batch, 1024 anchors per block */
#define NWARP_L (THR_L/32)

__device__ unsigned long long g_bp[NB*NT];   // packed (u_bits<<32)|~anchor_idx per (b,t)
__device__ unsigned char g_match[NB*NP];     // bit7 = pos, bits0-6 = best truth idx (UNforced)
__device__ unsigned g_binrank[NB*NP];        // (bin<<16) | rank-within-(block,bin)
__device__ int g_bcnt[NB*NBIN*BBLK];         // per-(batch,bin,block) counts
__device__ int g_ord[NB*NP];                 // anchor original indices in binned order
__device__ float4 g_part[NB*LBLKX];          // per-loss-block partials (sl, ce, cnt, 0)
__device__ unsigned g_ctr = 0;               // last-block detector (self-resetting)

// shared-memory histogram (zero global atomics) + g_bp init merged into block (0,0)
__global__ __launch_bounds__(256)
void k_hist(const float4* __restrict__ anchors){
    __shared__ int s_cnt[NBIN];
    const int b = blockIdx.y, blk = blockIdx.x, tid = threadIdx.x;
    if (blk == 0 && b == 0){
        for (int i = tid; i < NB*NT; i += 256) g_bp[i] = 0xFFFFFFFFull;
    }
    for (int i = tid; i < NBIN; i += 256) s_cnt[i] = 0;
    __syncthreads();
    const int base = blk*APB;
#pragma unroll
    for (int k = 0; k < APB/256; k++){
        int i = base + k*256 + tid;
        float4 a = anchors[b*NP + i];
        float cx = (a.x + a.z)*0.5f, cy = (a.y + a.w)*0.5f;
        int bx = min(GB-1, max(0, (int)(cx*(float)GB)));
        int by = min(GB-1, max(0, (int)(cy*(float)GB)));
        int bin = by*GB + bx;
        int r = atomicAdd(&s_cnt[bin], 1);
        g_binrank[b*NP + i] = ((unsigned)bin << 16) | (unsigned)r;
    }
    __syncthreads();
    for (int i = tid; i < NBIN; i += 256)
        g_bcnt[(b*NBIN + i)*BBLK + blk] = s_cnt[i];
}

// per-block redundant scan (counts L2-resident) + contention-free scatter
__global__ __launch_bounds__(NBIN)
void k_scatter(){
    __shared__ int s_tot[NBIN];
    __shared__ int s_base[NBIN];
    const int b = blockIdx.y, blk = blockIdx.x, tid = threadIdx.x;
    int myblkpref = 0, tot = 0;
#pragma unroll
    for (int k = 0; k < BBLK; k++){
        int c = g_bcnt[(b*NBIN + tid)*BBLK + k];
        if (k < blk) myblkpref += c;
        tot += c;
    }
    s_tot[tid] = tot;
    __syncthreads();
    for (int off = 1; off < NBIN; off <<= 1){
        int v = (tid >= off) ? s_tot[tid - off] : 0;
        __syncthreads();
        s_tot[tid] += v;
        __syncthreads();
    }
    s_base[tid] = (s_tot[tid] - tot) + myblkpref;
    __syncthreads();
    const int base = blk*APB;
#pragma unroll
    for (int k = 0; k < APB/NBIN; k++){
        int i = base + k*NBIN + tid;
        unsigned pr = g_binrank[b*NP + i];
        int bin = pr >> 16, r = pr & 0xFFFFu;
        g_ord[b*NP + s_base[bin] + r] = i;
    }
}

// R6-proven k_match: THR_M=256, APT=4, warp bbox prune + smem running-best filter
__global__ __launch_bounds__(THR_M)
void k_match(const float4* __restrict__ anchors, const float4* __restrict__ targets){
    const int b    = blockIdx.y;
    const int tid  = threadIdx.x;
    const int lane = tid & 31, wid = tid >> 5;
    const int slot0 = blockIdx.x*CHUNK + wid*128 + lane;

    __shared__ float4 s_tr[NT];
    __shared__ float  s_ta[NT];
    __shared__ unsigned long long s_key[NT];
    if (tid < NT){
        float4 t4 = targets[b*NT + tid];
        s_tr[tid]  = t4;
        s_ta[tid]  = (t4.z - t4.x) * (t4.w - t4.y);
        s_key[tid] = g_bp[b*NT + tid];         // seed filter from earlier blocks
    }
    __syncthreads();

    int oi[APT]; float4 A[APT]; float aa[APT];
    float bi[APT], bs[APT]; int bt[APT];
#pragma unroll
    for (int k = 0; k < APT; k++){
        oi[k] = g_ord[b*NP + slot0 + k*32];
        A[k]  = anchors[b*NP + oi[k]];
        aa[k] = (A[k].z - A[k].x) * (A[k].w - A[k].y);
        bi[k] = -1.0f; bs[k] = 1.0f; bt[k] = 0;
    }

    float wx1 = fminf(fminf(A[0].x, A[1].x), fminf(A[2].x, A[3].x));
    float wy1 = fminf(fminf(A[0].y, A[1].y), fminf(A[2].y, A[3].y));
    float wx2 = fmaxf(fmaxf(A[0].z, A[1].z), fmaxf(A[2].z, A[3].z));
    float wy2 = fmaxf(fmaxf(A[0].w, A[1].w), fmaxf(A[2].w, A[3].w));
#pragma unroll
    for (int off = 16; off > 0; off >>= 1){
        wx1 = fminf(wx1, __shfl_xor_sync(0xFFFFFFFFu, wx1, off));
        wy1 = fminf(wy1, __shfl_xor_sync(0xFFFFFFFFu, wy1, off));
        wx2 = fmaxf(wx2, __shfl_xor_sync(0xFFFFFFFFu, wx2, off));
        wy2 = fmaxf(wy2, __shfl_xor_sync(0xFFFFFFFFu, wy2, off));
    }

#pragma unroll 1
    for (int t = 0; t < NT; t++){
        float4 tr = s_tr[t];
        if (tr.x >= wx2 || tr.z <= wx1 || tr.y >= wy2 || tr.w <= wy1) continue;
        float atc = s_ta[t];
        unsigned long long cur = s_key[t];

        float li = 0.0f, ls = 1.0f; unsigned lg = 0;
#pragma unroll
        for (int k = 0; k < APT; k++){
            float w = fminf(tr.z, A[k].z) - fmaxf(tr.x, A[k].x);
            float h = fminf(tr.w, A[k].w) - fmaxf(tr.y, A[k].y);
            float inter4 = (w + fabsf(w)) * (h + fabsf(h));   // 4*inter, exact scale
            float S      = atc + aa[k];
            if (inter4 * bs[k] > bi[k] * S){ bi[k] = inter4; bs[k] = S; bt[k] = t; }
            if (inter4 * ls > li * S){ li = inter4; ls = S; lg = (unsigned)oi[k]; }
        }
        float ub = __uint_as_float((unsigned)(cur >> 32)) * 0.99999988f;
        if (li > 0.0f && li >= ub * ls){
            float u = __fdividef(li, ls);
            unsigned long long key =
                ((unsigned long long)__float_as_uint(u) << 32) | (unsigned long long)(~lg);
            atomicMax(&s_key[t], key);
        }
    }

#pragma unroll
    for (int k = 0; k < APT; k++){
        bool pos = (0.75f * bi[k] >= bs[k]);    // iou >= 0.5, identical rounding
        g_match[b*NP + oi[k]] =
            (unsigned char)((pos ? 0x80u : 0u) | (unsigned)bt[k]);
    }

    __syncthreads();
    if (tid < NT){
        unsigned long long key = s_key[tid];
        if (key) atomicMax(&g_bp[b*NT + tid], key);
    }
}

// smooth-L1 encode term: expression-identical in bulk pass and force-correction
__device__ __forceinline__ float slterm(float4 l, float4 a, float4 tr){
    float aw  = a.z - a.x,  ah  = a.w - a.y;
    float acx = (a.x + a.z)*0.5f, acy = (a.y + a.w)*0.5f;
    float mw  = tr.z - tr.x, mh = tr.w - tr.y;
    float mcx = (tr.x + tr.z)*0.5f, mcy = (tr.y + tr.w)*0.5f;
    float rw  = __fdividef(1.0f, aw), rh = __fdividef(1.0f, ah);
    float g0 = (mcx - acx) * rw * 10.0f;
    float g1 = (mcy - acy) * rh * 10.0f;
    float g2 = __logf(mw * rw) * 5.0f;
    float g3 = __logf(mh * rh) * 5.0f;
    float d0 = fabsf(l.x - g0), d1 = fabsf(l.y - g1);
    float d2 = fabsf(l.z - g2), d3 = fabsf(l.w - g3);
    float s = (d0 < 1.0f ? 0.5f*d0*d0 : d0 - 0.5f);
    s += (d1 < 1.0f ? 0.5f*d1*d1 : d1 - 0.5f);
    s += (d2 < 1.0f ? 0.5f*d2*d2 : d2 - 0.5f);
    s += (d3 < 1.0f ? 0.5f*d3*d3 : d3 - 0.5f);
    return s;
}

// atomic-free loss + fused force-match corrections + finalize (last-block pattern)
__global__ __launch_bounds__(THR_L)
void k_loss(const float4* __restrict__ loc, const float4* __restrict__ conf4,
            const float2* __restrict__ conf2,
            const float4* __restrict__ anchors, const float4* __restrict__ targets,
            float* __restrict__ out){
    const int b    = blockIdx.y;
    const int tid  = threadIdx.x;
    const int base = blockIdx.x * (THR_L*4) + tid*4;
    const int lane = tid & 31, wid = tid >> 5;

    __shared__ float4 s_tr[NT];
    if (tid < NT) s_tr[tid] = targets[b*NT + tid];
    __syncthreads();

    unsigned mu = *(const unsigned*)&g_match[b*NP + base];
    float4 c01 = conf4[(b*NP + base)/2 + 0];
    float4 c23 = conf4[(b*NP + base)/2 + 1];

    float sl = 0.0f, ce = 0.0f, cnt = 0.0f;
#pragma unroll
    for (int i = 0; i < 4; i++){
        unsigned m = (mu >> (8*i)) & 0xFFu;
        float x0, x1;
        if (i == 0){ x0 = c01.x; x1 = c01.y; }
        else if (i == 1){ x0 = c01.z; x1 = c01.w; }
        else if (i == 2){ x0 = c23.x; x1 = c23.y; }
        else { x0 = c23.z; x1 = c23.w; }
        // ce = (mx - x_label) + log1p(exp(mn-mx)); Schraudolph exp (no MUFU).
        // CE weight in output ~1.4e-5 => approximation error ~6e-7 relative.
        float mx = fmaxf(x0, x1), mn = fminf(x0, x1);
        float d  = fmaxf(mn - mx, -80.0f);
        float jf = fmaf(d, 12102203.0f, 1064866805.0f);
        float y  = __int_as_float((int)jf);
        float l1p = y*(1.0f - y*(0.5f - y*(0.33333333f - y*0.25f)));
        float xl  = (m & 0x80u) ? x1 : x0;
        ce += (mx - xl) + l1p;

        if (m & 0x80u){
            int p = base + i;
            sl += slterm(loc[b*NP + p], anchors[b*NP + p], s_tr[m & 0x7Fu]);
            cnt += 1.0f;
        }
    }

#pragma unroll
    for (int off = 16; off > 0; off >>= 1){
        sl  += __shfl_down_sync(0xFFFFFFFFu, sl,  off);
        ce  += __shfl_down_sync(0xFFFFFFFFu, ce,  off);
        cnt += __shfl_down_sync(0xFFFFFFFFu, cnt, off);
    }
    __shared__ float r0[NWARP_L], r1[NWARP_L], r2[NWARP_L];
    if (lane == 0){ r0[wid] = sl; r1[wid] = ce; r2[wid] = cnt; }
    __syncthreads();

    __shared__ unsigned s_last;
    if (tid == 0){
        float a = 0.f, c = 0.f, n = 0.f;
#pragma unroll
        for (int w = 0; w < NWARP_L; w++){ a += r0[w]; c += r1[w]; n += r2[w]; }
        g_part[b*LBLKX + blockIdx.x] = make_float4(a, c, n, 0.0f);
        __threadfence();
        unsigned v = atomicAdd(&g_ctr, 1u);
        s_last = (v == (unsigned)(NB*LBLKX) - 1u) ? 1u : 0u;
    }
    __syncthreads();
    if (!s_last) return;

    // ---------------- finish phase: only the LAST block runs this ----------------
    if (tid == 0) g_ctr = 0;                    // reset for next graph replay
    __shared__ unsigned s_win[NB*NT];
    for (int i = tid; i < NB*NT; i += THR_L)
        s_win[i] = ~((unsigned)(g_bp[i] & 0xFFFFFFFFull));
    __syncthreads();

    double dsl = 0.0, dce = 0.0, dcnt = 0.0;
#pragma unroll
    for (int q = 0; q < (NB*NT)/THR_L; q++){
        int i = q*THR_L + tid;
        int b2 = i >> 6, t = i & 63;
        unsigned idx = s_win[i];
        bool active = true;
        for (int t2 = t + 1; t2 < NT; t2++)
            if (s_win[(b2 << 6) | t2] == idx){ active = false; break; }  // last t wins
        if (active){
            unsigned m_old = g_match[b2*NP + idx];
            float2 c = conf2[b2*NP + idx];
            if (!(m_old & 0x80u)){ dce += (double)(c.x - c.y); dcnt += 1.0; } // label 0->1 (exact)
            float4 l = loc[b2*NP + idx], a = anchors[b2*NP + idx];
            float s = slterm(l, a, targets[b2*NT + t]);
            if (m_old & 0x80u)
                s -= slterm(l, a, targets[b2*NT + (int)(m_old & 0x7Fu)]); // exact cancellation
            dsl += (double)s;
        }
    }
    // fold all block partials (L1-bypass: other SMs wrote them)
    for (int i = tid; i < NB*LBLKX; i += THR_L){
        float4 p = __ldcg(&g_part[i]);
        dsl += (double)p.x; dce += (double)p.y; dcnt += (double)p.z;
    }

#pragma unroll
    for (int off = 16; off > 0; off >>= 1){
        dsl  += __shfl_down_sync(0xFFFFFFFFu, dsl,  off);
        dce  += __shfl_down_sync(0xFFFFFFFFu, dce,  off);
        dcnt += __shfl_down_sync(0xFFFFFFFFu, dcnt, off);
    }
    __shared__ double q0[NWARP_L], q1[NWARP_L], q2[NWARP_L];
    if (lane == 0){ q0[wid] = dsl; q1[wid] = dce; q2[wid] = dcnt; }
    __syncthreads();
    if (tid == 0){
        double a = 0.0, c = 0.0, n = 0.0;
#pragma unroll
        for (int w = 0; w < NWARP_L; w++){ a += q0[w]; c += q1[w]; n += q2[w]; }
        double loss = a / n + c / ((double)NP * (double)NB * (double)NP);
        out[0] = (float)loss;
    }
}

extern "C" void kernel_launch(void* const* d_in, const int* in_sizes, int n_in,
                              void* d_out, int out_size){
    const float4* loc     = (const float4*)d_in[0];
    const float4* conf4   = (const float4*)d_in[1];
    const float2* conf2   = (const float2*)d_in[1];
    const float4* anchors = (const float4*)d_in[2];
    const float4* targets = (const float4*)d_in[3];
    float* out = (float*)d_out;

    k_hist<<<dim3(BBLK, NB), 256>>>(anchors);                   // #1 (g_bp init merged)
    k_scatter<<<dim3(BBLK, NB), NBIN>>>();                      // #2
    k_match<<<dim3(NP/CHUNK, NB), THR_M>>>(anchors, targets);   // #3
    k_loss<<<dim3(LBLKX, NB), THR_L>>>(loc, conf4, conf2, anchors, targets, out); // #4 -> ncu
}

// round 11
// speedup vs baseline: 1.4113x; 1.4113x over previous
#include <cuda_runtime.h>

#define NB 16
#define NP 65536
#define NT 64
#define GB 16                 /* bins per dimension */
#define NBIN (GB*GB)          /* 256 bins per batch */
#define BBLK 16               /* binning blocks per batch */
#define APB (NP/BBLK)         /* 4096 anchors per binning block */

// ---- k_match config (R6 proven shape) ----
#define THR_M 256
#define APT 4
#define CHUNK (THR_M*APT)     /* 1024 anchors per block; each warp owns 128 binned slots */

// ---- k_loss config (R9 measured 9.8us shape) ----
#define THR_L 256
#define LBLKX (NP/(THR_L*4))  /* 64 blocks per batch, 1024 anchors per block */
#define NWARP_L (THR_L/32)

__device__ unsigned long long g_bp[NB*NT];   // packed (u_bits<<32)|~anchor_idx per (b,t)
__device__ unsigned char g_match[NB*NP];     // bit7 = pos, bits0-6 = best truth idx
__device__ unsigned g_binrank[NB*NP];        // (bin<<16) | rank-within-(block,bin)
__device__ int g_bcnt[NB*NBIN*BBLK];         // per-(batch,bin,block) counts
__device__ int g_ord[NB*NP];                 // anchor original indices in binned order
__device__ float4 g_part[NB*LBLKX];          // per-loss-block partials (sl, ce, cnt, 0)

// shared-memory histogram (zero global atomics) + g_bp init merged into block (0,0)
__global__ __launch_bounds__(256)
void k_hist(const float4* __restrict__ anchors){
    __shared__ int s_cnt[NBIN];
    const int b = blockIdx.y, blk = blockIdx.x, tid = threadIdx.x;
    if (blk == 0 && b == 0){
        for (int i = tid; i < NB*NT; i += 256) g_bp[i] = 0xFFFFFFFFull;
    }
    for (int i = tid; i < NBIN; i += 256) s_cnt[i] = 0;
    __syncthreads();
    const int base = blk*APB;
#pragma unroll
    for (int k = 0; k < APB/256; k++){
        int i = base + k*256 + tid;
        float4 a = anchors[b*NP + i];
        float cx = (a.x + a.z)*0.5f, cy = (a.y + a.w)*0.5f;
        int bx = min(GB-1, max(0, (int)(cx*(float)GB)));
        int by = min(GB-1, max(0, (int)(cy*(float)GB)));
        int bin = by*GB + bx;
        int r = atomicAdd(&s_cnt[bin], 1);
        g_binrank[b*NP + i] = ((unsigned)bin << 16) | (unsigned)r;
    }
    __syncthreads();
    for (int i = tid; i < NBIN; i += 256)
        g_bcnt[(b*NBIN + i)*BBLK + blk] = s_cnt[i];
}

// per-block redundant scan (counts L2-resident) + contention-free scatter
__global__ __launch_bounds__(NBIN)
void k_scatter(){
    __shared__ int s_tot[NBIN];
    __shared__ int s_base[NBIN];
    const int b = blockIdx.y, blk = blockIdx.x, tid = threadIdx.x;
    int myblkpref = 0, tot = 0;
#pragma unroll
    for (int k = 0; k < BBLK; k++){
        int c = g_bcnt[(b*NBIN + tid)*BBLK + k];
        if (k < blk) myblkpref += c;
        tot += c;
    }
    s_tot[tid] = tot;
    __syncthreads();
    for (int off = 1; off < NBIN; off <<= 1){
        int v = (tid >= off) ? s_tot[tid - off] : 0;
        __syncthreads();
        s_tot[tid] += v;
        __syncthreads();
    }
    s_base[tid] = (s_tot[tid] - tot) + myblkpref;
    __syncthreads();
    const int base = blk*APB;
#pragma unroll
    for (int k = 0; k < APB/NBIN; k++){
        int i = base + k*NBIN + tid;
        unsigned pr = g_binrank[b*NP + i];
        int bin = pr >> 16, r = pr & 0xFFFFu;
        g_ord[b*NP + s_base[bin] + r] = i;
    }
}

// R6-proven k_match: THR_M=256, APT=4, warp bbox prune + smem running-best filter
__global__ __launch_bounds__(THR_M)
void k_match(const float4* __restrict__ anchors, const float4* __restrict__ targets){
    const int b    = blockIdx.y;
    const int tid  = threadIdx.x;
    const int lane = tid & 31, wid = tid >> 5;
    const int slot0 = blockIdx.x*CHUNK + wid*128 + lane;

    __shared__ float4 s_tr[NT];
    __shared__ float  s_ta[NT];
    __shared__ unsigned long long s_key[NT];
    if (tid < NT){
        float4 t4 = targets[b*NT + tid];
        s_tr[tid]  = t4;
        s_ta[tid]  = (t4.z - t4.x) * (t4.w - t4.y);
        s_key[tid] = g_bp[b*NT + tid];         // seed filter from earlier blocks
    }
    __syncthreads();

    int oi[APT]; float4 A[APT]; float aa[APT];
    float bi[APT], bs[APT]; int bt[APT];
#pragma unroll
    for (int k = 0; k < APT; k++){
        oi[k] = g_ord[b*NP + slot0 + k*32];
        A[k]  = anchors[b*NP + oi[k]];
        aa[k] = (A[k].z - A[k].x) * (A[k].w - A[k].y);
        bi[k] = -1.0f; bs[k] = 1.0f; bt[k] = 0;
    }

    float wx1 = fminf(fminf(A[0].x, A[1].x), fminf(A[2].x, A[3].x));
    float wy1 = fminf(fminf(A[0].y, A[1].y), fminf(A[2].y, A[3].y));
    float wx2 = fmaxf(fmaxf(A[0].z, A[1].z), fmaxf(A[2].z, A[3].z));
    float wy2 = fmaxf(fmaxf(A[0].w, A[1].w), fmaxf(A[2].w, A[3].w));
#pragma unroll
    for (int off = 16; off > 0; off >>= 1){
        wx1 = fminf(wx1, __shfl_xor_sync(0xFFFFFFFFu, wx1, off));
        wy1 = fminf(wy1, __shfl_xor_sync(0xFFFFFFFFu, wy1, off));
        wx2 = fmaxf(wx2, __shfl_xor_sync(0xFFFFFFFFu, wx2, off));
        wy2 = fmaxf(wy2, __shfl_xor_sync(0xFFFFFFFFu, wy2, off));
    }

#pragma unroll 1
    for (int t = 0; t < NT; t++){
        float4 tr = s_tr[t];
        if (tr.x >= wx2 || tr.z <= wx1 || tr.y >= wy2 || tr.w <= wy1) continue;
        float atc = s_ta[t];
        unsigned long long cur = s_key[t];

        float li = 0.0f, ls = 1.0f; unsigned lg = 0;
#pragma unroll
        for (int k = 0; k < APT; k++){
            float w = fminf(tr.z, A[k].z) - fmaxf(tr.x, A[k].x);
            float h = fminf(tr.w, A[k].w) - fmaxf(tr.y, A[k].y);
            float inter4 = (w + fabsf(w)) * (h + fabsf(h));   // 4*inter, exact scale
            float S      = atc + aa[k];
            if (inter4 * bs[k] > bi[k] * S){ bi[k] = inter4; bs[k] = S; bt[k] = t; }
            if (inter4 * ls > li * S){ li = inter4; ls = S; lg = (unsigned)oi[k]; }
        }
        float ub = __uint_as_float((unsigned)(cur >> 32)) * 0.99999988f;
        if (li > 0.0f && li >= ub * ls){
            float u = __fdividef(li, ls);
            unsigned long long key =
                ((unsigned long long)__float_as_uint(u) << 32) | (unsigned long long)(~lg);
            atomicMax(&s_key[t], key);
        }
    }

#pragma unroll
    for (int k = 0; k < APT; k++){
        bool pos = (0.75f * bi[k] >= bs[k]);    // iou >= 0.5, identical rounding
        g_match[b*NP + oi[k]] =
            (unsigned char)((pos ? 0x80u : 0u) | (unsigned)bt[k]);
    }

    __syncthreads();
    if (tid < NT){
        unsigned long long key = s_key[tid];
        if (key) atomicMax(&g_bp[b*NT + tid], key);
    }
}

// parallel force-match: 16 blocks x 64 threads, smem backward-scan dedupe
// (last t wins on duplicate winner anchors, matching the torch loop)
__global__ __launch_bounds__(NT)
void k_force(){
    __shared__ unsigned s_win[NT];
    const int b = blockIdx.x, t = threadIdx.x;
    s_win[t] = ~((unsigned)(g_bp[b*NT + t] & 0xFFFFFFFFull));
    __syncthreads();
    unsigned idx = s_win[t];
    bool active = true;
    for (int t2 = t + 1; t2 < NT; t2++)
        if (s_win[t2] == idx){ active = false; break; }
    if (active)
        g_match[b*NP + idx] = (unsigned char)(0x80u | (unsigned)t);
}

// smooth-L1 encode term
__device__ __forceinline__ float slterm(float4 l, float4 a, float4 tr){
    float aw  = a.z - a.x,  ah  = a.w - a.y;
    float acx = (a.x + a.z)*0.5f, acy = (a.y + a.w)*0.5f;
    float mw  = tr.z - tr.x, mh = tr.w - tr.y;
    float mcx = (tr.x + tr.z)*0.5f, mcy = (tr.y + tr.w)*0.5f;
    float rw  = __fdividef(1.0f, aw), rh = __fdividef(1.0f, ah);
    float g0 = (mcx - acx) * rw * 10.0f;
    float g1 = (mcy - acy) * rh * 10.0f;
    float g2 = __logf(mw * rw) * 5.0f;
    float g3 = __logf(mh * rh) * 5.0f;
    float d0 = fabsf(l.x - g0), d1 = fabsf(l.y - g1);
    float d2 = fabsf(l.z - g2), d3 = fabsf(l.w - g3);
    float s = (d0 < 1.0f ? 0.5f*d0*d0 : d0 - 0.5f);
    s += (d1 < 1.0f ? 0.5f*d1*d1 : d1 - 0.5f);
    s += (d2 < 1.0f ? 0.5f*d2*d2 : d2 - 0.5f);
    s += (d3 < 1.0f ? 0.5f*d3*d3 : d3 - 0.5f);
    return s;
}

// atomic-free loss on FORCED matches (R9 bulk, measured 9.8us): partials to g_part
__global__ __launch_bounds__(THR_L)
void k_loss(const float4* __restrict__ loc, const float4* __restrict__ conf4,
            const float4* __restrict__ anchors, const float4* __restrict__ targets){
    const int b    = blockIdx.y;
    const int tid  = threadIdx.x;
    const int base = blockIdx.x * (THR_L*4) + tid*4;

    __shared__ float4 s_tr[NT];
    if (tid < NT) s_tr[tid] = targets[b*NT + tid];
    __syncthreads();

    unsigned mu = *(const unsigned*)&g_match[b*NP + base];
    float4 c01 = conf4[(b*NP + base)/2 + 0];
    float4 c23 = conf4[(b*NP + base)/2 + 1];

    float sl = 0.0f, ce = 0.0f, cnt = 0.0f;
#pragma unroll
    for (int i = 0; i < 4; i++){
        unsigned m = (mu >> (8*i)) & 0xFFu;
        float x0, x1;
        if (i == 0){ x0 = c01.x; x1 = c01.y; }
        else if (i == 1){ x0 = c01.z; x1 = c01.w; }
        else if (i == 2){ x0 = c23.x; x1 = c23.y; }
        else { x0 = c23.z; x1 = c23.w; }
        // ce = (mx - x_label) + log1p(exp(mn-mx)); Schraudolph exp (no MUFU).
        // CE weight in output ~1.4e-5 => approximation error ~6e-7 relative.
        float mx = fmaxf(x0, x1), mn = fminf(x0, x1);
        float d  = fmaxf(mn - mx, -80.0f);
        float jf = fmaf(d, 12102203.0f, 1064866805.0f);
        float y  = __int_as_float((int)jf);
        float l1p = y*(1.0f - y*(0.5f - y*(0.33333333f - y*0.25f)));
        float xl  = (m & 0x80u) ? x1 : x0;
        ce += (mx - xl) + l1p;

        if (m & 0x80u){
            int p = base + i;
            sl += slterm(loc[b*NP + p], anchors[b*NP + p], s_tr[m & 0x7Fu]);
            cnt += 1.0f;
        }
    }

#pragma unroll
    for (int off = 16; off > 0; off >>= 1){
        sl  += __shfl_down_sync(0xFFFFFFFFu, sl,  off);
        ce  += __shfl_down_sync(0xFFFFFFFFu, ce,  off);
        cnt += __shfl_down_sync(0xFFFFFFFFu, cnt, off);
    }
    __shared__ float r0[NWARP_L], r1[NWARP_L], r2[NWARP_L];
    int lane = tid & 31, wid = tid >> 5;
    if (lane == 0){ r0[wid] = sl; r1[wid] = ce; r2[wid] = cnt; }
    __syncthreads();
    if (tid == 0){
        float a = 0.f, c = 0.f, n = 0.f;
#pragma unroll
        for (int w = 0; w < NWARP_L; w++){ a += r0[w]; c += r1[w]; n += r2[w]; }
        g_part[b*LBLKX + blockIdx.x] = make_float4(a, c, n, 0.0f);
    }
}

// reduce 1024 partials in double, finalize (no fences, no scattered gathers)
__global__ __launch_bounds__(1024)
void k_fin(float* __restrict__ out){
    const int tid = threadIdx.x;
    float4 p = g_part[tid];                    // NB*LBLKX == 1024, one each
    double dsl = (double)p.x, dce = (double)p.y, dcnt = (double)p.z;
#pragma unroll
    for (int off = 16; off > 0; off >>= 1){
        dsl  += __shfl_down_sync(0xFFFFFFFFu, dsl,  off);
        dce  += __shfl_down_sync(0xFFFFFFFFu, dce,  off);
        dcnt += __shfl_down_sync(0xFFFFFFFFu, dcnt, off);
    }
    __shared__ double q0[32], q1[32], q2[32];
    int lane = tid & 31, wid = tid >> 5;
    if (lane == 0){ q0[wid] = dsl; q1[wid] = dce; q2[wid] = dcnt; }
    __syncthreads();
    if (tid == 0){
        double a = 0.0, c = 0.0, n = 0.0;
#pragma unroll
        for (int w = 0; w < 32; w++){ a += q0[w]; c += q1[w]; n += q2[w]; }
        double loss = a / n + c / ((double)NP * (double)NB * (double)NP);
        out[0] = (float)loss;
    }
}

extern "C" void kernel_launch(void* const* d_in, const int* in_sizes, int n_in,
                              void* d_out, int out_size){
    const float4* loc     = (const float4*)d_in[0];
    const float4* conf4   = (const float4*)d_in[1];
    const float4* anchors = (const float4*)d_in[2];
    const float4* targets = (const float4*)d_in[3];
    float* out = (float*)d_out;

    k_hist<<<dim3(BBLK, NB), 256>>>(anchors);                   // #1 (g_bp init merged)
    k_scatter<<<dim3(BBLK, NB), NBIN>>>();                      // #2
    k_match<<<dim3(NP/CHUNK, NB), THR_M>>>(anchors, targets);   // #3
    k_force<<<NB, NT>>>();                                      // #4 -> ncu slot
    k_loss<<<dim3(LBLKX, NB), THR_L>>>(loc, conf4, anchors, targets);  // #5
    k_fin<<<1, 1024>>>(out);                                    // #6
}

// round 12
// speedup vs baseline: 1.5487x; 1.0973x over previous
#include <cuda_runtime.h>

#define NB 16
#define NP 65536
#define NT 64
#define GB 16                 /* bins per dimension */
#define NBIN (GB*GB)          /* 256 bins per batch */
#define BBLK 16               /* binning blocks per batch */
#define APB (NP/BBLK)         /* 4096 anchors per binning block */

// ---- k_match config ----
#define THR_M 256
#define APT 4
#define CHUNK (THR_M*APT)     /* 1024 anchors per block; each warp owns 128 binned slots */

// ---- k_loss config (R9/R11 measured ~9.8us shape) ----
#define THR_L 256
#define LBLKX (NP/(THR_L*4))  /* 64 blocks per batch, 1024 anchors per block */
#define NWARP_L (THR_L/32)

__device__ unsigned long long g_bp[NB*NT];   // packed (u_bits<<32)|~anchor_idx per (b,t)
__device__ unsigned char g_match[NB*NP];     // bit7 = pos, bits0-6 = best truth idx
__device__ unsigned g_binrank[NB*NP];        // (bin<<16) | rank-within-(block,bin)
__device__ int g_bcnt[NB*NBIN*BBLK];         // per-(batch,bin,block) counts
__device__ int g_ord[NB*NP];                 // anchor original indices in binned order
__device__ float4 g_part[NB*LBLKX];          // per-loss-block partials (sl, ce, cnt, 0)

// shared-memory histogram (zero global atomics) + g_bp init merged into block (0,0)
__global__ __launch_bounds__(256)
void k_hist(const float4* __restrict__ anchors){
    __shared__ int s_cnt[NBIN];
    const int b = blockIdx.y, blk = blockIdx.x, tid = threadIdx.x;
    if (blk == 0 && b == 0){
        for (int i = tid; i < NB*NT; i += 256) g_bp[i] = 0xFFFFFFFFull;
    }
    for (int i = tid; i < NBIN; i += 256) s_cnt[i] = 0;
    __syncthreads();
    const int base = blk*APB;
#pragma unroll
    for (int k = 0; k < APB/256; k++){
        int i = base + k*256 + tid;
        float4 a = anchors[b*NP + i];
        float cx = (a.x + a.z)*0.5f, cy = (a.y + a.w)*0.5f;
        int bx = min(GB-1, max(0, (int)(cx*(float)GB)));
        int by = min(GB-1, max(0, (int)(cy*(float)GB)));
        int bin = by*GB + bx;
        int r = atomicAdd(&s_cnt[bin], 1);
        g_binrank[b*NP + i] = ((unsigned)bin << 16) | (unsigned)r;
    }
    __syncthreads();
    for (int i = tid; i < NBIN; i += 256)
        g_bcnt[(b*NBIN + i)*BBLK + blk] = s_cnt[i];
}

// per-block redundant scan (counts L2-resident) + contention-free scatter
__global__ __launch_bounds__(NBIN)
void k_scatter(){
    __shared__ int s_tot[NBIN];
    __shared__ int s_base[NBIN];
    const int b = blockIdx.y, blk = blockIdx.x, tid = threadIdx.x;
    int myblkpref = 0, tot = 0;
#pragma unroll
    for (int k = 0; k < BBLK; k++){
        int c = g_bcnt[(b*NBIN + tid)*BBLK + k];
        if (k < blk) myblkpref += c;
        tot += c;
    }
    s_tot[tid] = tot;
    __syncthreads();
    for (int off = 1; off < NBIN; off <<= 1){
        int v = (tid >= off) ? s_tot[tid - off] : 0;
        __syncthreads();
        s_tot[tid] += v;
        __syncthreads();
    }
    s_base[tid] = (s_tot[tid] - tot) + myblkpref;
    __syncthreads();
    const int base = blk*APB;
#pragma unroll
    for (int k = 0; k < APB/NBIN; k++){
        int i = base + k*NBIN + tid;
        unsigned pr = g_binrank[b*NP + i];
        int bin = pr >> 16, r = pr & 0xFFFFu;
        g_ord[b*NP + s_base[bin] + r] = i;
    }
}

// k_match: warp bbox prune with ballot-precomputed 64-bit truth mask,
// ffs-walk over overlapping truths only, smem running-best filter.
__global__ __launch_bounds__(THR_M)
void k_match(const float4* __restrict__ anchors, const float4* __restrict__ targets){
    const int b    = blockIdx.y;
    const int tid  = threadIdx.x;
    const int lane = tid & 31, wid = tid >> 5;
    const int slot0 = blockIdx.x*CHUNK + wid*128 + lane;

    __shared__ float4 s_tr[NT];
    __shared__ float  s_ta[NT];
    __shared__ unsigned long long s_key[NT];
    if (tid < NT){
        float4 t4 = targets[b*NT + tid];
        s_tr[tid]  = t4;
        s_ta[tid]  = (t4.z - t4.x) * (t4.w - t4.y);
        s_key[tid] = g_bp[b*NT + tid];         // seed filter from earlier blocks
    }
    __syncthreads();

    int oi[APT]; float4 A[APT]; float aa[APT];
    float bi[APT], bs[APT]; int bt[APT];
#pragma unroll
    for (int k = 0; k < APT; k++){
        oi[k] = g_ord[b*NP + slot0 + k*32];
        A[k]  = anchors[b*NP + oi[k]];
        aa[k] = (A[k].z - A[k].x) * (A[k].w - A[k].y);
        bi[k] = -1.0f; bs[k] = 1.0f; bt[k] = 0;
    }

    // warp bbox over this warp's 128 spatially-local anchors
    float wx1 = fminf(fminf(A[0].x, A[1].x), fminf(A[2].x, A[3].x));
    float wy1 = fminf(fminf(A[0].y, A[1].y), fminf(A[2].y, A[3].y));
    float wx2 = fmaxf(fmaxf(A[0].z, A[1].z), fmaxf(A[2].z, A[3].z));
    float wy2 = fmaxf(fmaxf(A[0].w, A[1].w), fmaxf(A[2].w, A[3].w));
#pragma unroll
    for (int off = 16; off > 0; off >>= 1){
        wx1 = fminf(wx1, __shfl_xor_sync(0xFFFFFFFFu, wx1, off));
        wy1 = fminf(wy1, __shfl_xor_sync(0xFFFFFFFFu, wy1, off));
        wx2 = fmaxf(wx2, __shfl_xor_sync(0xFFFFFFFFu, wx2, off));
        wy2 = fmaxf(wy2, __shfl_xor_sync(0xFFFFFFFFu, wy2, off));
    }

    // ballot-precomputed overlap mask: lane tests truths lane and lane+32
    // (identical condition to the old per-t branch; warp-uniform by construction)
    unsigned long long mask;
    {
        float4 t0 = s_tr[lane];
        float4 t1 = s_tr[lane + 32];
        bool v0 = !(t0.x >= wx2 || t0.z <= wx1 || t0.y >= wy2 || t0.w <= wy1);
        bool v1 = !(t1.x >= wx2 || t1.z <= wx1 || t1.y >= wy2 || t1.w <= wy1);
        unsigned m0 = __ballot_sync(0xFFFFFFFFu, v0);
        unsigned m1 = __ballot_sync(0xFFFFFFFFu, v1);
        mask = (unsigned long long)m0 | ((unsigned long long)m1 << 32);
    }

    while (mask){
        const int t = __ffsll((long long)mask) - 1;
        mask &= mask - 1;
        float4 tr = s_tr[t];
        float atc = s_ta[t];
        unsigned long long cur = s_key[t];

        float li = 0.0f, ls = 1.0f; unsigned lg = 0;
#pragma unroll
        for (int k = 0; k < APT; k++){
            float w = fminf(tr.z, A[k].z) - fmaxf(tr.x, A[k].x);
            float h = fminf(tr.w, A[k].w) - fmaxf(tr.y, A[k].y);
            float inter4 = (w + fabsf(w)) * (h + fabsf(h));   // 4*inter, exact scale
            float S      = atc + aa[k];
            if (inter4 * bs[k] > bi[k] * S){ bi[k] = inter4; bs[k] = S; bt[k] = t; }
            if (inter4 * ls > li * S){ li = inter4; ls = S; lg = (unsigned)oi[k]; }
        }
        // running-best filter: stale reads only admit extra attempts; 2-ulp slack
        float ub = __uint_as_float((unsigned)(cur >> 32)) * 0.99999988f;
        if (li > 0.0f && li >= ub * ls){
            float u = __fdividef(li, ls);
            unsigned long long key =
                ((unsigned long long)__float_as_uint(u) << 32) | (unsigned long long)(~lg);
            atomicMax(&s_key[t], key);
        }
    }

#pragma unroll
    for (int k = 0; k < APT; k++){
        bool pos = (0.75f * bi[k] >= bs[k]);    // iou >= 0.5, identical rounding
        g_match[b*NP + oi[k]] =
            (unsigned char)((pos ? 0x80u : 0u) | (unsigned)bt[k]);
    }

    __syncthreads();
    if (tid < NT){
        unsigned long long key = s_key[tid];
        if (key) atomicMax(&g_bp[b*NT + tid], key);
    }
}

// parallel force-match: 16 blocks x 64 threads, smem backward-scan dedupe
// (last t wins on duplicate winner anchors, matching the torch loop)
__global__ __launch_bounds__(NT)
void k_force(){
    __shared__ unsigned s_win[NT];
    const int b = blockIdx.x, t = threadIdx.x;
    s_win[t] = ~((unsigned)(g_bp[b*NT + t] & 0xFFFFFFFFull));
    __syncthreads();
    unsigned idx = s_win[t];
    bool active = true;
    for (int t2 = t + 1; t2 < NT; t2++)
        if (s_win[t2] == idx){ active = false; break; }
    if (active)
        g_match[b*NP + idx] = (unsigned char)(0x80u | (unsigned)t);
}

// smooth-L1 encode term
__device__ __forceinline__ float slterm(float4 l, float4 a, float4 tr){
    float aw  = a.z - a.x,  ah  = a.w - a.y;
    float acx = (a.x + a.z)*0.5f, acy = (a.y + a.w)*0.5f;
    float mw  = tr.z - tr.x, mh = tr.w - tr.y;
    float mcx = (tr.x + tr.z)*0.5f, mcy = (tr.y + tr.w)*0.5f;
    float rw  = __fdividef(1.0f, aw), rh = __fdividef(1.0f, ah);
    float g0 = (mcx - acx) * rw * 10.0f;
    float g1 = (mcy - acy) * rh * 10.0f;
    float g2 = __logf(mw * rw) * 5.0f;
    float g3 = __logf(mh * rh) * 5.0f;
    float d0 = fabsf(l.x - g0), d1 = fabsf(l.y - g1);
    float d2 = fabsf(l.z - g2), d3 = fabsf(l.w - g3);
    float s = (d0 < 1.0f ? 0.5f*d0*d0 : d0 - 0.5f);
    s += (d1 < 1.0f ? 0.5f*d1*d1 : d1 - 0.5f);
    s += (d2 < 1.0f ? 0.5f*d2*d2 : d2 - 0.5f);
    s += (d3 < 1.0f ? 0.5f*d3*d3 : d3 - 0.5f);
    return s;
}

// atomic-free loss on FORCED matches: partials to g_part
__global__ __launch_bounds__(THR_L)
void k_loss(const float4* __restrict__ loc, const float4* __restrict__ conf4,
            const float4* __restrict__ anchors, const float4* __restrict__ targets){
    const int b    = blockIdx.y;
    const int tid  = threadIdx.x;
    const int base = blockIdx.x * (THR_L*4) + tid*4;

    __shared__ float4 s_tr[NT];
    if (tid < NT) s_tr[tid] = targets[b*NT + tid];
    __syncthreads();

    unsigned mu = *(const unsigned*)&g_match[b*NP + base];
    float4 c01 = conf4[(b*NP + base)/2 + 0];
    float4 c23 = conf4[(b*NP + base)/2 + 1];

    float sl = 0.0f, ce = 0.0f, cnt = 0.0f;
#pragma unroll
    for (int i = 0; i < 4; i++){
        unsigned m = (mu >> (8*i)) & 0xFFu;
        float x0, x1;
        if (i == 0){ x0 = c01.x; x1 = c01.y; }
        else if (i == 1){ x0 = c01.z; x1 = c01.w; }
        else if (i == 2){ x0 = c23.x; x1 = c23.y; }
        else { x0 = c23.z; x1 = c23.w; }
        // ce = (mx - x_label) + log1p(exp(mn-mx)); Schraudolph exp (no MUFU).
        // CE weight in output ~1.4e-5 => approximation error ~6e-7 relative.
        float mx = fmaxf(x0, x1), mn = fminf(x0, x1);
        float d  = fmaxf(mn - mx, -80.0f);
        float jf = fmaf(d, 12102203.0f, 1064866805.0f);
        float y  = __int_as_float((int)jf);
        float l1p = y*(1.0f - y*(0.5f - y*(0.33333333f - y*0.25f)));
        float xl  = (m & 0x80u) ? x1 : x0;
        ce += (mx - xl) + l1p;

        if (m & 0x80u){
            int p = base + i;
            sl += slterm(loc[b*NP + p], anchors[b*NP + p], s_tr[m & 0x7Fu]);
            cnt += 1.0f;
        }
    }

#pragma unroll
    for (int off = 16; off > 0; off >>= 1){
        sl  += __shfl_down_sync(0xFFFFFFFFu, sl,  off);
        ce  += __shfl_down_sync(0xFFFFFFFFu, ce,  off);
        cnt += __shfl_down_sync(0xFFFFFFFFu, cnt, off);
    }
    __shared__ float r0[NWARP_L], r1[NWARP_L], r2[NWARP_L];
    int lane = tid & 31, wid = tid >> 5;
    if (lane == 0){ r0[wid] = sl; r1[wid] = ce; r2[wid] = cnt; }
    __syncthreads();
    if (tid == 0){
        float a = 0.f, c = 0.f, n = 0.f;
#pragma unroll
        for (int w = 0; w < NWARP_L; w++){ a += r0[w]; c += r1[w]; n += r2[w]; }
        g_part[b*LBLKX + blockIdx.x] = make_float4(a, c, n, 0.0f);
    }
}

// reduce 1024 partials in double, finalize
__global__ __launch_bounds__(1024)
void k_fin(float* __restrict__ out){
    const int tid = threadIdx.x;
    float4 p = g_part[tid];                    // NB*LBLKX == 1024, one each
    double dsl = (double)p.x, dce = (double)p.y, dcnt = (double)p.z;
#pragma unroll
    for (int off = 16; off > 0; off >>= 1){
        dsl  += __shfl_down_sync(0xFFFFFFFFu, dsl,  off);
        dce  += __shfl_down_sync(0xFFFFFFFFu, dce,  off);
        dcnt += __shfl_down_sync(0xFFFFFFFFu, dcnt, off);
    }
    __shared__ double q0[32], q1[32], q2[32];
    int lane = tid & 31, wid = tid >> 5;
    if (lane == 0){ q0[wid] = dsl; q1[wid] = dce; q2[wid] = dcnt; }
    __syncthreads();
    if (tid == 0){
        double a = 0.0, c = 0.0, n = 0.0;
#pragma unroll
        for (int w = 0; w < 32; w++){ a += q0[w]; c += q1[w]; n += q2[w]; }
        double loss = a / n + c / ((double)NP * (double)NB * (double)NP);
        out[0] = (float)loss;
    }
}

extern "C" void kernel_launch(void* const* d_in, const int* in_sizes, int n_in,
                              void* d_out, int out_size){
    const float4* loc     = (const float4*)d_in[0];
    const float4* conf4   = (const float4*)d_in[1];
    const float4* anchors = (const float4*)d_in[2];
    const float4* targets = (const float4*)d_in[3];
    float* out = (float*)d_out;

    k_hist<<<dim3(BBLK, NB), 256>>>(anchors);                   // #1 (g_bp init merged)
    k_scatter<<<dim3(BBLK, NB), NBIN>>>();                      // #2
    k_match<<<dim3(NP/CHUNK, NB), THR_M>>>(anchors, targets);   // #3
    k_force<<<NB, NT>>>();                                      // #4 -> ncu slot
    k_loss<<<dim3(LBLKX, NB), THR_L>>>(loc, conf4, anchors, targets);  // #5
    k_fin<<<1, 1024>>>(out);                                    // #6
}

// round 13
// speedup vs baseline: 1.6018x; 1.0343x over previous
#include <cuda_runtime.h>

#define NB 16
#define NP 65536
#define NT 64
#define GB 16                 /* bins per dimension */
#define NBIN (GB*GB)          /* 256 bins per batch */
#define BBLK 16               /* binning blocks per batch */
#define APB (NP/BBLK)         /* 4096 anchors per binning block */

// ---- k_match config ----
#define THR_M 256
#define APT 4
#define CHUNK (THR_M*APT)     /* 1024 anchors per block; each warp owns 128 binned slots */

// ---- k_loss config ----
#define THR_L 256
#define LBLKX (NP/(THR_L*4))  /* 64 blocks per batch, 1024 anchors per block */
#define NWARP_L (THR_L/32)

__device__ unsigned long long g_bp[NB*NT];   // packed (u_bits<<32)|~anchor_idx per (b,t)
__device__ unsigned char g_match[NB*NP];     // bit7 = pos, bits0-6 = best truth idx (UNforced)
__device__ unsigned g_binrank[NB*NP];        // (bin<<16) | rank-within-(block,bin)
__device__ int g_bcnt[NB*NBIN*BBLK];         // per-(batch,bin,block) counts
__device__ int g_ord[NB*NP];                 // anchor original indices in binned order
__device__ float4 g_part[NB*LBLKX];          // per-loss-block partials (sl, ce, cnt, 0)

// shared-memory histogram (zero global atomics) + g_bp init merged into block (0,0)
__global__ __launch_bounds__(256)
void k_hist(const float4* __restrict__ anchors){
    __shared__ int s_cnt[NBIN];
    const int b = blockIdx.y, blk = blockIdx.x, tid = threadIdx.x;
    if (blk == 0 && b == 0){
        for (int i = tid; i < NB*NT; i += 256) g_bp[i] = 0xFFFFFFFFull;
    }
    for (int i = tid; i < NBIN; i += 256) s_cnt[i] = 0;
    __syncthreads();
    const int base = blk*APB;
#pragma unroll
    for (int k = 0; k < APB/256; k++){
        int i = base + k*256 + tid;
        float4 a = anchors[b*NP + i];
        float cx = (a.x + a.z)*0.5f, cy = (a.y + a.w)*0.5f;
        int bx = min(GB-1, max(0, (int)(cx*(float)GB)));
        int by = min(GB-1, max(0, (int)(cy*(float)GB)));
        int bin = by*GB + bx;
        int r = atomicAdd(&s_cnt[bin], 1);
        g_binrank[b*NP + i] = ((unsigned)bin << 16) | (unsigned)r;
    }
    __syncthreads();
    for (int i = tid; i < NBIN; i += 256)
        g_bcnt[(b*NBIN + i)*BBLK + blk] = s_cnt[i];
}

// per-block redundant scan (counts L2-resident) + contention-free scatter
__global__ __launch_bounds__(NBIN)
void k_scatter(){
    __shared__ int s_tot[NBIN];
    __shared__ int s_base[NBIN];
    const int b = blockIdx.y, blk = blockIdx.x, tid = threadIdx.x;
    int myblkpref = 0, tot = 0;
#pragma unroll
    for (int k = 0; k < BBLK; k++){
        int c = g_bcnt[(b*NBIN + tid)*BBLK + k];
        if (k < blk) myblkpref += c;
        tot += c;
    }
    s_tot[tid] = tot;
    __syncthreads();
    for (int off = 1; off < NBIN; off <<= 1){
        int v = (tid >= off) ? s_tot[tid - off] : 0;
        __syncthreads();
        s_tot[tid] += v;
        __syncthreads();
    }
    s_base[tid] = (s_tot[tid] - tot) + myblkpref;
    __syncthreads();
    const int base = blk*APB;
#pragma unroll
    for (int k = 0; k < APB/NBIN; k++){
        int i = base + k*NBIN + tid;
        unsigned pr = g_binrank[b*NP + i];
        int bin = pr >> 16, r = pr & 0xFFFFu;
        g_ord[b*NP + s_base[bin] + r] = i;
    }
}

// k_match: warp bbox prune with ballot-precomputed 64-bit truth mask,
// ffs-walk over overlapping truths only, smem running-best filter.
__global__ __launch_bounds__(THR_M)
void k_match(const float4* __restrict__ anchors, const float4* __restrict__ targets){
    const int b    = blockIdx.y;
    const int tid  = threadIdx.x;
    const int lane = tid & 31, wid = tid >> 5;
    const int slot0 = blockIdx.x*CHUNK + wid*128 + lane;

    __shared__ float4 s_tr[NT];
    __shared__ float  s_ta[NT];
    __shared__ unsigned long long s_key[NT];
    if (tid < NT){
        float4 t4 = targets[b*NT + tid];
        s_tr[tid]  = t4;
        s_ta[tid]  = (t4.z - t4.x) * (t4.w - t4.y);
        s_key[tid] = g_bp[b*NT + tid];         // seed filter from earlier blocks
    }
    __syncthreads();

    int oi[APT]; float4 A[APT]; float aa[APT];
    float bi[APT], bs[APT]; int bt[APT];
#pragma unroll
    for (int k = 0; k < APT; k++){
        oi[k] = g_ord[b*NP + slot0 + k*32];
        A[k]  = anchors[b*NP + oi[k]];
        aa[k] = (A[k].z - A[k].x) * (A[k].w - A[k].y);
        bi[k] = -1.0f; bs[k] = 1.0f; bt[k] = 0;
    }

    // warp bbox over this warp's 128 spatially-local anchors
    float wx1 = fminf(fminf(A[0].x, A[1].x), fminf(A[2].x, A[3].x));
    float wy1 = fminf(fminf(A[0].y, A[1].y), fminf(A[2].y, A[3].y));
    float wx2 = fmaxf(fmaxf(A[0].z, A[1].z), fmaxf(A[2].z, A[3].z));
    float wy2 = fmaxf(fmaxf(A[0].w, A[1].w), fmaxf(A[2].w, A[3].w));
#pragma unroll
    for (int off = 16; off > 0; off >>= 1){
        wx1 = fminf(wx1, __shfl_xor_sync(0xFFFFFFFFu, wx1, off));
        wy1 = fminf(wy1, __shfl_xor_sync(0xFFFFFFFFu, wy1, off));
        wx2 = fmaxf(wx2, __shfl_xor_sync(0xFFFFFFFFu, wx2, off));
        wy2 = fmaxf(wy2, __shfl_xor_sync(0xFFFFFFFFu, wy2, off));
    }

    // ballot-precomputed overlap mask: lane tests truths lane and lane+32
    unsigned long long mask;
    {
        float4 t0 = s_tr[lane];
        float4 t1 = s_tr[lane + 32];
        bool v0 = !(t0.x >= wx2 || t0.z <= wx1 || t0.y >= wy2 || t0.w <= wy1);
        bool v1 = !(t1.x >= wx2 || t1.z <= wx1 || t1.y >= wy2 || t1.w <= wy1);
        unsigned m0 = __ballot_sync(0xFFFFFFFFu, v0);
        unsigned m1 = __ballot_sync(0xFFFFFFFFu, v1);
        mask = (unsigned long long)m0 | ((unsigned long long)m1 << 32);
    }

    while (mask){
        const int t = __ffsll((long long)mask) - 1;
        mask &= mask - 1;
        float4 tr = s_tr[t];
        float atc = s_ta[t];
        unsigned long long cur = s_key[t];

        float li = 0.0f, ls = 1.0f; unsigned lg = 0;
#pragma unroll
        for (int k = 0; k < APT; k++){
            float w = fminf(tr.z, A[k].z) - fmaxf(tr.x, A[k].x);
            float h = fminf(tr.w, A[k].w) - fmaxf(tr.y, A[k].y);
            float inter4 = (w + fabsf(w)) * (h + fabsf(h));   // 4*inter, exact scale
            float S      = atc + aa[k];
            if (inter4 * bs[k] > bi[k] * S){ bi[k] = inter4; bs[k] = S; bt[k] = t; }
            if (inter4 * ls > li * S){ li = inter4; ls = S; lg = (unsigned)oi[k]; }
        }
        // running-best filter: stale reads only admit extra attempts; 2-ulp slack
        float ub = __uint_as_float((unsigned)(cur >> 32)) * 0.99999988f;
        if (li > 0.0f && li >= ub * ls){
            float u = __fdividef(li, ls);
            unsigned long long key =
                ((unsigned long long)__float_as_uint(u) << 32) | (unsigned long long)(~lg);
            atomicMax(&s_key[t], key);
        }
    }

#pragma unroll
    for (int k = 0; k < APT; k++){
        bool pos = (0.75f * bi[k] >= bs[k]);    // iou >= 0.5, identical rounding
        g_match[b*NP + oi[k]] =
            (unsigned char)((pos ? 0x80u : 0u) | (unsigned)bt[k]);
    }

    __syncthreads();
    if (tid < NT){
        unsigned long long key = s_key[tid];
        if (key) atomicMax(&g_bp[b*NT + tid], key);
    }
}

// smooth-L1 encode term
__device__ __forceinline__ float slterm(float4 l, float4 a, float4 tr){
    float aw  = a.z - a.x,  ah  = a.w - a.y;
    float acx = (a.x + a.z)*0.5f, acy = (a.y + a.w)*0.5f;
    float mw  = tr.z - tr.x, mh = tr.w - tr.y;
    float mcx = (tr.x + tr.z)*0.5f, mcy = (tr.y + tr.w)*0.5f;
    float rw  = __fdividef(1.0f, aw), rh = __fdividef(1.0f, ah);
    float g0 = (mcx - acx) * rw * 10.0f;
    float g1 = (mcy - acy) * rh * 10.0f;
    float g2 = __logf(mw * rw) * 5.0f;
    float g3 = __logf(mh * rh) * 5.0f;
    float d0 = fabsf(l.x - g0), d1 = fabsf(l.y - g1);
    float d2 = fabsf(l.z - g2), d3 = fabsf(l.w - g3);
    float s = (d0 < 1.0f ? 0.5f*d0*d0 : d0 - 0.5f);
    s += (d1 < 1.0f ? 0.5f*d1*d1 : d1 - 0.5f);
    s += (d2 < 1.0f ? 0.5f*d2*d2 : d2 - 0.5f);
    s += (d3 < 1.0f ? 0.5f*d3*d3 : d3 - 0.5f);
    return s;
}

// atomic-free loss with INLINE force-match patch (replaces the k_force launch):
// each block redundantly dedupes its batch's 64 winners (last t wins) and
// overrides the g_match bytes for winners inside its 1024-anchor range.
__global__ __launch_bounds__(THR_L)
void k_loss(const float4* __restrict__ loc, const float4* __restrict__ conf4,
            const float4* __restrict__ anchors, const float4* __restrict__ targets){
    const int b    = blockIdx.y;
    const int tid  = threadIdx.x;
    const int blk0 = blockIdx.x * (THR_L*4);        // block's first anchor
    const int base = blk0 + tid*4;

    __shared__ float4 s_tr[NT];
    __shared__ unsigned s_win[NT];
    __shared__ unsigned char s_patch[THR_L*4];      // 0xFF = no override
    if (tid < NT){
        s_tr[tid]  = targets[b*NT + tid];
        s_win[tid] = ~((unsigned)(g_bp[b*NT + tid] & 0xFFFFFFFFull));
    }
    *(unsigned*)&s_patch[tid*4] = 0xFFFFFFFFu;
    __syncthreads();
    if (tid < NT){
        unsigned idx = s_win[tid];
        bool active = true;
        for (int t2 = tid + 1; t2 < NT; t2++)
            if (s_win[t2] == idx){ active = false; break; }    // last t wins
        if (active && idx >= (unsigned)blk0 && idx < (unsigned)(blk0 + THR_L*4))
            s_patch[idx - blk0] = (unsigned char)(0x80u | (unsigned)tid);
    }
    __syncthreads();

    unsigned mu = *(const unsigned*)&g_match[b*NP + base];
    unsigned pu = *(unsigned*)&s_patch[tid*4];
    float4 c01 = conf4[(b*NP + base)/2 + 0];
    float4 c23 = conf4[(b*NP + base)/2 + 1];

    float sl = 0.0f, ce = 0.0f, cnt = 0.0f;
#pragma unroll
    for (int i = 0; i < 4; i++){
        unsigned p8 = (pu >> (8*i)) & 0xFFu;
        unsigned m  = (p8 != 0xFFu) ? p8 : ((mu >> (8*i)) & 0xFFu);
        float x0, x1;
        if (i == 0){ x0 = c01.x; x1 = c01.y; }
        else if (i == 1){ x0 = c01.z; x1 = c01.w; }
        else if (i == 2){ x0 = c23.x; x1 = c23.y; }
        else { x0 = c23.z; x1 = c23.w; }
        // ce = (mx - x_label) + log1p(exp(mn-mx)); Schraudolph exp (no MUFU).
        // CE weight in output ~1.4e-5 => approximation error ~6e-7 relative.
        float mx = fmaxf(x0, x1), mn = fminf(x0, x1);
        float d  = fmaxf(mn - mx, -80.0f);
        float jf = fmaf(d, 12102203.0f, 1064866805.0f);
        float y  = __int_as_float((int)jf);
        float l1p = y*(1.0f - y*(0.5f - y*(0.33333333f - y*0.25f)));
        float xl  = (m & 0x80u) ? x1 : x0;
        ce += (mx - xl) + l1p;

        if (m & 0x80u){
            int p = base + i;
            sl += slterm(loc[b*NP + p], anchors[b*NP + p], s_tr[m & 0x7Fu]);
            cnt += 1.0f;
        }
    }

#pragma unroll
    for (int off = 16; off > 0; off >>= 1){
        sl  += __shfl_down_sync(0xFFFFFFFFu, sl,  off);
        ce  += __shfl_down_sync(0xFFFFFFFFu, ce,  off);
        cnt += __shfl_down_sync(0xFFFFFFFFu, cnt, off);
    }
    __shared__ float r0[NWARP_L], r1[NWARP_L], r2[NWARP_L];
    int lane = tid & 31, wid = tid >> 5;
    if (lane == 0){ r0[wid] = sl; r1[wid] = ce; r2[wid] = cnt; }
    __syncthreads();
    if (tid == 0){
        float a = 0.f, c = 0.f, n = 0.f;
#pragma unroll
        for (int w = 0; w < NWARP_L; w++){ a += r0[w]; c += r1[w]; n += r2[w]; }
        g_part[b*LBLKX + blockIdx.x] = make_float4(a, c, n, 0.0f);
    }
}

// reduce 1024 partials in double, finalize
__global__ __launch_bounds__(1024)
void k_fin(float* __restrict__ out){
    const int tid = threadIdx.x;
    float4 p = g_part[tid];                    // NB*LBLKX == 1024, one each
    double dsl = (double)p.x, dce = (double)p.y, dcnt = (double)p.z;
#pragma unroll
    for (int off = 16; off > 0; off >>= 1){
        dsl  += __shfl_down_sync(0xFFFFFFFFu, dsl,  off);
        dce  += __shfl_down_sync(0xFFFFFFFFu, dce,  off);
        dcnt += __shfl_down_sync(0xFFFFFFFFu, dcnt, off);
    }
    __shared__ double q0[32], q1[32], q2[32];
    int lane = tid & 31, wid = tid >> 5;
    if (lane == 0){ q0[wid] = dsl; q1[wid] = dce; q2[wid] = dcnt; }
    __syncthreads();
    if (tid == 0){
        double a = 0.0, c = 0.0, n = 0.0;
#pragma unroll
        for (int w = 0; w < 32; w++){ a += q0[w]; c += q1[w]; n += q2[w]; }
        double loss = a / n + c / ((double)NP * (double)NB * (double)NP);
        out[0] = (float)loss;
    }
}

extern "C" void kernel_launch(void* const* d_in, const int* in_sizes, int n_in,
                              void* d_out, int out_size){
    const float4* loc     = (const float4*)d_in[0];
    const float4* conf4   = (const float4*)d_in[1];
    const float4* anchors = (const float4*)d_in[2];
    const float4* targets = (const float4*)d_in[3];
    float* out = (float*)d_out;

    k_hist<<<dim3(BBLK, NB), 256>>>(anchors);                   // #1 (g_bp init merged)
    k_scatter<<<dim3(BBLK, NB), NBIN>>>();                      // #2
    k_match<<<dim3(NP/CHUNK, NB), THR_M>>>(anchors, targets);   // #3
    k_loss<<<dim3(LBLKX, NB), THR_L>>>(loc, conf4, anchors, targets);  // #4 -> ncu slot
    k_fin<<<1, 1024>>>(out);                                    // #5
}

// round 14
// speedup vs baseline: 1.6615x; 1.0373x over previous
#include <cuda_runtime.h>

#define NB 16
#define NP 65536
#define NT 64
#define GB 16                 /* bins per dimension */
#define NBIN (GB*GB)          /* 256 bins per batch */
#define BBLK 16               /* binning blocks per batch */
#define APB (NP/BBLK)         /* 4096 anchors per binning block */

// ---- k_match config ----
#define THR_M 128
#define APT 4
#define CHUNK (THR_M*APT)     /* 512 anchors per block; each warp owns 128 binned slots */

// ---- k_loss config ----
#define THR_L 256
#define APL 8                 /* anchors per thread */
#define LBLK2 (NP/(THR_L*APL))/* 32 blocks per batch, 2048 anchors per block */
#define NWARP_L (THR_L/32)

__device__ unsigned long long g_bp[NB*NT];   // packed (u_bits<<32)|~anchor_idx per (b,t)
__device__ unsigned char g_match[NB*NP];     // bit7 = pos, bits0-6 = best truth idx (UNforced)
__device__ unsigned g_binrank[NB*NP];        // (bin<<16) | rank-within-(block,bin)
__device__ int g_bcnt[NB*NBIN*BBLK];         // per-(batch,bin,block) counts
__device__ int g_ord[NB*NP];                 // anchor original indices in binned order
__device__ float4 g_part[NB*LBLK2];          // per-loss-block partials (sl, ce, cnt, 0)

// shared-memory histogram (zero global atomics) + g_bp init merged into block (0,0)
__global__ __launch_bounds__(256)
void k_hist(const float4* __restrict__ anchors){
    __shared__ int s_cnt[NBIN];
    const int b = blockIdx.y, blk = blockIdx.x, tid = threadIdx.x;
    if (blk == 0 && b == 0){
        for (int i = tid; i < NB*NT; i += 256) g_bp[i] = 0xFFFFFFFFull;
    }
    for (int i = tid; i < NBIN; i += 256) s_cnt[i] = 0;
    __syncthreads();
    const int base = blk*APB;
#pragma unroll
    for (int k = 0; k < APB/256; k++){
        int i = base + k*256 + tid;
        float4 a = anchors[b*NP + i];
        float cx = (a.x + a.z)*0.5f, cy = (a.y + a.w)*0.5f;
        int bx = min(GB-1, max(0, (int)(cx*(float)GB)));
        int by = min(GB-1, max(0, (int)(cy*(float)GB)));
        int bin = by*GB + bx;
        int r = atomicAdd(&s_cnt[bin], 1);
        g_binrank[b*NP + i] = ((unsigned)bin << 16) | (unsigned)r;
    }
    __syncthreads();
    for (int i = tid; i < NBIN; i += 256)
        g_bcnt[(b*NBIN + i)*BBLK + blk] = s_cnt[i];
}

// per-block redundant scan (counts L2-resident) + contention-free scatter
__global__ __launch_bounds__(NBIN)
void k_scatter(){
    __shared__ int s_tot[NBIN];
    __shared__ int s_base[NBIN];
    const int b = blockIdx.y, blk = blockIdx.x, tid = threadIdx.x;
    int myblkpref = 0, tot = 0;
#pragma unroll
    for (int k = 0; k < BBLK; k++){
        int c = g_bcnt[(b*NBIN + tid)*BBLK + k];
        if (k < blk) myblkpref += c;
        tot += c;
    }
    s_tot[tid] = tot;
    __syncthreads();
    for (int off = 1; off < NBIN; off <<= 1){
        int v = (tid >= off) ? s_tot[tid - off] : 0;
        __syncthreads();
        s_tot[tid] += v;
        __syncthreads();
    }
    s_base[tid] = (s_tot[tid] - tot) + myblkpref;
    __syncthreads();
    const int base = blk*APB;
#pragma unroll
    for (int k = 0; k < APB/NBIN; k++){
        int i = base + k*NBIN + tid;
        unsigned pr = g_binrank[b*NP + i];
        int bin = pr >> 16, r = pr & 0xFFFFu;
        g_ord[b*NP + s_base[bin] + r] = i;
    }
}

// k_match: warp bbox prune + ballot mask + ffs-walk; 9 blocks/SM via reg squeeze
// (filter reads only high word of s_key; original indices re-fetched on demand)
__global__ __launch_bounds__(THR_M, 9)
void k_match(const float4* __restrict__ anchors, const float4* __restrict__ targets){
    const int b    = blockIdx.y;
    const int tid  = threadIdx.x;
    const int lane = tid & 31, wid = tid >> 5;
    const int slot0 = blockIdx.x*CHUNK + wid*128 + lane;

    __shared__ float4 s_tr[NT];
    __shared__ float  s_ta[NT];
    __shared__ unsigned long long s_key[NT];
    if (tid < NT){
        float4 t4 = targets[b*NT + tid];
        s_tr[tid]  = t4;
        s_ta[tid]  = (t4.z - t4.x) * (t4.w - t4.y);
        s_key[tid] = g_bp[b*NT + tid];         // seed filter from earlier blocks
    }
    __syncthreads();

    float4 A[APT]; float aa[APT];
    float bi[APT], bs[APT]; int bt[APT];
#pragma unroll
    for (int k = 0; k < APT; k++){
        int o = g_ord[b*NP + slot0 + k*32];    // not kept live across the loop
        A[k]  = anchors[b*NP + o];
        aa[k] = (A[k].z - A[k].x) * (A[k].w - A[k].y);
        bi[k] = -1.0f; bs[k] = 1.0f; bt[k] = 0;
    }

    // warp bbox over this warp's 128 spatially-local anchors
    float wx1 = fminf(fminf(A[0].x, A[1].x), fminf(A[2].x, A[3].x));
    float wy1 = fminf(fminf(A[0].y, A[1].y), fminf(A[2].y, A[3].y));
    float wx2 = fmaxf(fmaxf(A[0].z, A[1].z), fmaxf(A[2].z, A[3].z));
    float wy2 = fmaxf(fmaxf(A[0].w, A[1].w), fmaxf(A[2].w, A[3].w));
#pragma unroll
    for (int off = 16; off > 0; off >>= 1){
        wx1 = fminf(wx1, __shfl_xor_sync(0xFFFFFFFFu, wx1, off));
        wy1 = fminf(wy1, __shfl_xor_sync(0xFFFFFFFFu, wy1, off));
        wx2 = fmaxf(wx2, __shfl_xor_sync(0xFFFFFFFFu, wx2, off));
        wy2 = fmaxf(wy2, __shfl_xor_sync(0xFFFFFFFFu, wy2, off));
    }

    // ballot-precomputed overlap mask: lane tests truths lane and lane+32
    unsigned long long mask;
    {
        float4 t0 = s_tr[lane];
        float4 t1 = s_tr[lane + 32];
        bool v0 = !(t0.x >= wx2 || t0.z <= wx1 || t0.y >= wy2 || t0.w <= wy1);
        bool v1 = !(t1.x >= wx2 || t1.z <= wx1 || t1.y >= wy2 || t1.w <= wy1);
        unsigned m0 = __ballot_sync(0xFFFFFFFFu, v0);
        unsigned m1 = __ballot_sync(0xFFFFFFFFu, v1);
        mask = (unsigned long long)m0 | ((unsigned long long)m1 << 32);
    }

    while (mask){
        const int t = __ffsll((long long)mask) - 1;
        mask &= mask - 1;
        float4 tr = s_tr[t];
        float atc = s_ta[t];
        unsigned cu = ((const unsigned*)&s_key[t])[1];   // high word: u_bits only

        float li = 0.0f, ls = 1.0f; int lk = 0;
#pragma unroll
        for (int k = 0; k < APT; k++){
            float w = fminf(tr.z, A[k].z) - fmaxf(tr.x, A[k].x);
            float h = fminf(tr.w, A[k].w) - fmaxf(tr.y, A[k].y);
            float inter4 = (w + fabsf(w)) * (h + fabsf(h));   // 4*inter, exact scale
            float S      = atc + aa[k];
            if (inter4 * bs[k] > bi[k] * S){ bi[k] = inter4; bs[k] = S; bt[k] = t; }
            if (inter4 * ls > li * S){ li = inter4; ls = S; lk = k; }
        }
        // running-best filter: stale reads only admit extra attempts; 2-ulp slack
        float ub = __uint_as_float(cu) * 0.99999988f;
        if (li > 0.0f && li >= ub * ls){
            float u = __fdividef(li, ls);
            unsigned gidx = (unsigned)g_ord[b*NP + slot0 + lk*32];  // rare branch
            unsigned long long key =
                ((unsigned long long)__float_as_uint(u) << 32) | (unsigned long long)(~gidx);
            atomicMax(&s_key[t], key);
        }
    }

#pragma unroll
    for (int k = 0; k < APT; k++){
        bool pos = (0.75f * bi[k] >= bs[k]);    // iou >= 0.5, identical rounding
        int o = g_ord[b*NP + slot0 + k*32];     // L1-hot reload
        g_match[b*NP + o] =
            (unsigned char)((pos ? 0x80u : 0u) | (unsigned)bt[k]);
    }

    __syncthreads();
    if (tid < NT){
        unsigned long long key = s_key[tid];
        if (key) atomicMax(&g_bp[b*NT + tid], key);
    }
}

// smooth-L1 encode term
__device__ __forceinline__ float slterm(float4 l, float4 a, float4 tr){
    float aw  = a.z - a.x,  ah  = a.w - a.y;
    float acx = (a.x + a.z)*0.5f, acy = (a.y + a.w)*0.5f;
    float mw  = tr.z - tr.x, mh = tr.w - tr.y;
    float mcx = (tr.x + tr.z)*0.5f, mcy = (tr.y + tr.w)*0.5f;
    float rw  = __fdividef(1.0f, aw), rh = __fdividef(1.0f, ah);
    float g0 = (mcx - acx) * rw * 10.0f;
    float g1 = (mcy - acy) * rh * 10.0f;
    float g2 = __logf(mw * rw) * 5.0f;
    float g3 = __logf(mh * rh) * 5.0f;
    float d0 = fabsf(l.x - g0), d1 = fabsf(l.y - g1);
    float d2 = fabsf(l.z - g2), d3 = fabsf(l.w - g3);
    float s = (d0 < 1.0f ? 0.5f*d0*d0 : d0 - 0.5f);
    s += (d1 < 1.0f ? 0.5f*d1*d1 : d1 - 0.5f);
    s += (d2 < 1.0f ? 0.5f*d2*d2 : d2 - 0.5f);
    s += (d3 < 1.0f ? 0.5f*d3*d3 : d3 - 0.5f);
    return s;
}

// atomic-free loss, 8 anchors/thread (2x MLP), inline force-match patch
__global__ __launch_bounds__(THR_L)
void k_loss(const float4* __restrict__ loc, const float4* __restrict__ conf4,
            const float4* __restrict__ anchors, const float4* __restrict__ targets){
    const int b    = blockIdx.y;
    const int tid  = threadIdx.x;
    const int blk0 = blockIdx.x * (THR_L*APL);      // block's first anchor (2048 range)
    const int base = blk0 + tid*APL;

    __shared__ float4 s_tr[NT];
    __shared__ unsigned s_win[NT];
    __shared__ unsigned char s_patch[THR_L*APL];    // 0xFF = no override
    if (tid < NT){
        s_tr[tid]  = targets[b*NT + tid];
        s_win[tid] = ~((unsigned)(g_bp[b*NT + tid] & 0xFFFFFFFFull));
    }
    *(uint2*)&s_patch[tid*APL] = make_uint2(0xFFFFFFFFu, 0xFFFFFFFFu);
    __syncthreads();
    if (tid < NT){
        unsigned idx = s_win[tid];
        bool active = true;
        for (int t2 = tid + 1; t2 < NT; t2++)
            if (s_win[t2] == idx){ active = false; break; }    // last t wins
        if (active && idx >= (unsigned)blk0 && idx < (unsigned)(blk0 + THR_L*APL))
            s_patch[idx - blk0] = (unsigned char)(0x80u | (unsigned)tid);
    }
    __syncthreads();

    // front-loaded loads: 2x match words + 4x conf float4 (high MLP)
    uint2 mu2 = *(const uint2*)&g_match[b*NP + base];
    float4 c0 = conf4[(b*NP + base)/2 + 0];
    float4 c1 = conf4[(b*NP + base)/2 + 1];
    float4 c2 = conf4[(b*NP + base)/2 + 2];
    float4 c3 = conf4[(b*NP + base)/2 + 3];
    uint2 p2  = *(uint2*)&s_patch[tid*APL];

    float cf[16];
    cf[0]=c0.x; cf[1]=c0.y; cf[2]=c0.z; cf[3]=c0.w;
    cf[4]=c1.x; cf[5]=c1.y; cf[6]=c1.z; cf[7]=c1.w;
    cf[8]=c2.x; cf[9]=c2.y; cf[10]=c2.z; cf[11]=c2.w;
    cf[12]=c3.x; cf[13]=c3.y; cf[14]=c3.z; cf[15]=c3.w;

    float sl = 0.0f, ce = 0.0f, cnt = 0.0f;
#pragma unroll
    for (int i = 0; i < APL; i++){
        unsigned mw8 = (i < 4) ? (mu2.x >> (8*i)) : (mu2.y >> (8*(i-4)));
        unsigned pw8 = (i < 4) ? (p2.x  >> (8*i)) : (p2.y  >> (8*(i-4)));
        unsigned p8 = pw8 & 0xFFu;
        unsigned m  = (p8 != 0xFFu) ? p8 : (mw8 & 0xFFu);
        float x0 = cf[2*i], x1 = cf[2*i + 1];
        // ce = (mx - x_label) + log1p(exp(mn-mx)); Schraudolph exp (no MUFU).
        // CE weight in output ~1.4e-5 => approximation error ~6e-7 relative.
        float mx = fmaxf(x0, x1), mn = fminf(x0, x1);
        float d  = fmaxf(mn - mx, -80.0f);
        float jf = fmaf(d, 12102203.0f, 1064866805.0f);
        float y  = __int_as_float((int)jf);
        float l1p = y*(1.0f - y*(0.5f - y*(0.33333333f - y*0.25f)));
        float xl  = (m & 0x80u) ? x1 : x0;
        ce += (mx - xl) + l1p;

        if (m & 0x80u){
            int p = base + i;
            sl += slterm(loc[b*NP + p], anchors[b*NP + p], s_tr[m & 0x7Fu]);
            cnt += 1.0f;
        }
    }

#pragma unroll
    for (int off = 16; off > 0; off >>= 1){
        sl  += __shfl_down_sync(0xFFFFFFFFu, sl,  off);
        ce  += __shfl_down_sync(0xFFFFFFFFu, ce,  off);
        cnt += __shfl_down_sync(0xFFFFFFFFu, cnt, off);
    }
    __shared__ float r0[NWARP_L], r1[NWARP_L], r2[NWARP_L];
    int lane = tid & 31, wid = tid >> 5;
    if (lane == 0){ r0[wid] = sl; r1[wid] = ce; r2[wid] = cnt; }
    __syncthreads();
    if (tid == 0){
        float a = 0.f, c = 0.f, n = 0.f;
#pragma unroll
        for (int w = 0; w < NWARP_L; w++){ a += r0[w]; c += r1[w]; n += r2[w]; }
        g_part[b*LBLK2 + blockIdx.x] = make_float4(a, c, n, 0.0f);
    }
}

// reduce 512 partials in double, finalize
__global__ __launch_bounds__(512)
void k_fin(float* __restrict__ out){
    const int tid = threadIdx.x;
    float4 p = g_part[tid];                    // NB*LBLK2 == 512, one each
    double dsl = (double)p.x, dce = (double)p.y, dcnt = (double)p.z;
#pragma unroll
    for (int off = 16; off > 0; off >>= 1){
        dsl  += __shfl_down_sync(0xFFFFFFFFu, dsl,  off);
        dce  += __shfl_down_sync(0xFFFFFFFFu, dce,  off);
        dcnt += __shfl_down_sync(0xFFFFFFFFu, dcnt, off);
    }
    __shared__ double q0[16], q1[16], q2[16];
    int lane = tid & 31, wid = tid >> 5;
    if (lane == 0){ q0[wid] = dsl; q1[wid] = dce; q2[wid] = dcnt; }
    __syncthreads();
    if (tid == 0){
        double a = 0.0, c = 0.0, n = 0.0;
#pragma unroll
        for (int w = 0; w < 16; w++){ a += q0[w]; c += q1[w]; n += q2[w]; }
        double loss = a / n + c / ((double)NP * (double)NB * (double)NP);
        out[0] = (float)loss;
    }
}

extern "C" void kernel_launch(void* const* d_in, const int* in_sizes, int n_in,
                              void* d_out, int out_size){
    const float4* loc     = (const float4*)d_in[0];
    const float4* conf4   = (const float4*)d_in[1];
    const float4* anchors = (const float4*)d_in[2];
    const float4* targets = (const float4*)d_in[3];
    float* out = (float*)d_out;

    k_hist<<<dim3(BBLK, NB), 256>>>(anchors);                   // #1 (g_bp init merged)
    k_scatter<<<dim3(BBLK, NB), NBIN>>>();                      // #2
    k_match<<<dim3(NP/CHUNK, NB), THR_M>>>(anchors, targets);   // #3
    k_loss<<<dim3(LBLK2, NB), THR_L>>>(loc, conf4, anchors, targets);  // #4 -> ncu slot
    k_fin<<<1, 512>>>(out);                                     // #5
}